// round 5
// baseline (speedup 1.0000x reference)
#include <cuda_runtime.h>
#include <cuda_bf16.h>
#include <cstdint>

// Problem constants: B=512, conv in [512,128,1024], k=5 VALID -> L=1020
// LSTM1 H=32 (in 128), LSTM2 H=16 (in 32), LSTM3 H=32 (in 16). Out: [512,32].
#define BATCH 512
#define TSEQ  1020
#define MROWS (BATCH * TSEQ)   // 522240

// ---------------------------------------------------------------------------
// Device scratch (no runtime allocation allowed). ~1.04 GB total.
// ---------------------------------------------------------------------------
__device__ __align__(256) float g_conv[66846720];  // [B][128][1020] flat == A1 [M][128]
__device__ __align__(256) float g_xg1 [66846720];  // [M][128] gate-permuted
__device__ __align__(256) float g_h1  [16711680];  // [M][32]
__device__ __align__(256) float g_xg2 [33423360];  // [M][64] gate-permuted
__device__ __align__(256) float g_h2  [ 8355840];  // [M][16]
__device__ __align__(256) float g_xg3 [66846720];  // [M][128] gate-permuted
__device__ __align__(256) float g_w1p [16384];     // [128][128] permuted Wih1
__device__ __align__(256) float g_b1p [128];
__device__ __align__(256) float g_w2p [2048];      // [64][32]
__device__ __align__(256) float g_b2p [64];
__device__ __align__(256) float g_w3p [2048];      // [128][16]
__device__ __align__(256) float g_b3p [128];

__device__ __forceinline__ float sigf(float x) {
    return __fdividef(1.0f, 1.0f + __expf(-x));
}
__device__ __forceinline__ float tanha(float x) {
    // tanh(x) = 2*sigmoid(2x) - 1 ; correct saturation for large |x|
    return 2.0f * __fdividef(1.0f, 1.0f + __expf(-2.0f * x)) - 1.0f;
}

// ---------------------------------------------------------------------------
// Gate permutation: Wp[p][k] with p = l*4 + j  (j in {i,f,g,o}), source row j*H+l.
// Also folds bih+bhh into bp[p].
// ---------------------------------------------------------------------------
__global__ void k_perm(const float* __restrict__ Wih, const float* __restrict__ bih,
                       const float* __restrict__ bhh, float* __restrict__ Wp,
                       float* __restrict__ bp, int H, int K) {
    int idx = blockIdx.x * 256 + threadIdx.x;
    int N = 4 * H;
    if (idx < N * K) {
        int p = idx / K, k = idx % K;
        int j = p & 3, l = p >> 2;
        Wp[idx] = Wih[(j * H + l) * K + k];
    }
    if (idx < N) {
        int j = idx & 3, l = idx >> 2;
        bp[idx] = bih[j * H + l] + bhh[j * H + l];
    }
}

// ---------------------------------------------------------------------------
// conv1d VALID k=5: out[b][oc][l] = cb[oc] + sum_{ic,k} x[b][ic][l+k]*w[oc][ic][k]
// Tile: 64 oc x 64 l per block, thread tile 4x4, ic chunks of 8 in smem.
// ---------------------------------------------------------------------------
__global__ __launch_bounds__(256) void k_conv(const float* __restrict__ x,
                                              const float* __restrict__ w,
                                              const float* __restrict__ cb,
                                              float* __restrict__ out) {
    __shared__ float xs[8][68];
    __shared__ float ws[64][40];
    const int t  = threadIdx.x;
    const int tx = t & 15;        // 16 l-thread groups (4 l each)
    const int ty = t >> 4;        // 16 oc-thread groups (4 oc each)
    const int l0  = blockIdx.x * 64;
    const int oc0 = blockIdx.y * 64;
    const int b   = blockIdx.z;
    const float* xb = x + (size_t)b * 131072;   // 128*1024

    float acc[4][4];
#pragma unroll
    for (int o = 0; o < 4; o++)
#pragma unroll
        for (int j = 0; j < 4; j++) acc[o][j] = 0.f;

    for (int ic0 = 0; ic0 < 128; ic0 += 8) {
        for (int idx = t; idx < 8 * 68; idx += 256) {
            int ic = idx / 68, col = idx % 68;
            int gcol = l0 + col;
            xs[ic][col] = (gcol < 1024) ? xb[(ic0 + ic) * 1024 + gcol] : 0.f;
        }
        for (int idx = t; idx < 64 * 40; idx += 256) {
            int oc = idx / 40, rem = idx % 40;
            ws[oc][rem] = w[(oc0 + oc) * 640 + ic0 * 5 + rem];
        }
        __syncthreads();
#pragma unroll
        for (int ic = 0; ic < 8; ic++) {
#pragma unroll
            for (int k = 0; k < 5; k++) {
                float xv[4], wv[4];
#pragma unroll
                for (int j = 0; j < 4; j++) xv[j] = xs[ic][tx * 4 + j + k];
#pragma unroll
                for (int o = 0; o < 4; o++) wv[o] = ws[ty * 4 + o][ic * 5 + k];
#pragma unroll
                for (int o = 0; o < 4; o++)
#pragma unroll
                    for (int j = 0; j < 4; j++) acc[o][j] += wv[o] * xv[j];
            }
        }
        __syncthreads();
    }
#pragma unroll
    for (int o = 0; o < 4; o++) {
        int oc = oc0 + ty * 4 + o;
        float bias = cb[oc];
#pragma unroll
        for (int j = 0; j < 4; j++) {
            int l = l0 + tx * 4 + j;
            if (l < TSEQ)
                out[(size_t)b * 130560 + (size_t)oc * TSEQ + l] = acc[o][j] + bias;
        }
    }
}

// ---------------------------------------------------------------------------
// Xg[m][p] = bp[p] + sum_k A[m][k] * Wp[p*K+k]   (A row-major [M][K])
// Tile: 64 rows x N cols, 256 threads. N in {128,64}, K in {128,32,16}.
// ---------------------------------------------------------------------------
template <int N, int K>
__global__ __launch_bounds__(256) void k_gemm(const float* __restrict__ A,
                                              const float* __restrict__ Wp,
                                              const float* __restrict__ bp,
                                              float* __restrict__ Xg) {
    constexpr int KC  = 16;
    constexpr int CG  = N / 4;      // col-thread count (each 4 cols)
    constexpr int RG  = 256 / CG;   // row-thread groups
    constexpr int RPT = 64 / RG;    // rows per thread
    __shared__ float As[64][KC];
    __shared__ float Ws[KC][N];

    const int t  = threadIdx.x;
    const int cg = t % CG;
    const int rg = t / CG;
    const size_t m0 = (size_t)blockIdx.x * 64;

    float acc[RPT][4];
#pragma unroll
    for (int r = 0; r < RPT; r++)
#pragma unroll
        for (int j = 0; j < 4; j++) acc[r][j] = 0.f;

    for (int kc = 0; kc < K; kc += KC) {
        {   // A tile: 64x16 floats = 256 float4, one per thread (coalesced)
            int row = t >> 2;
            int k4  = (t & 3) * 4;
            float4 v = *(const float4*)&A[(m0 + row) * K + kc + k4];
            *(float4*)&As[row][k4] = v;
        }
#pragma unroll
        for (int e = 0; e < N * KC / 256; e++) {   // W tile, transposed into smem
            int idx = t + e * 256;
            int p = idx % N;
            int kk = idx / N;
            Ws[kk][p] = Wp[p * K + kc + kk];
        }
        __syncthreads();
#pragma unroll
        for (int kk = 0; kk < KC; kk++) {
            float4 w4 = *(const float4*)&Ws[kk][cg * 4];
#pragma unroll
            for (int r = 0; r < RPT; r++) {
                float av = As[rg * RPT + r][kk];
                acc[r][0] += av * w4.x;
                acc[r][1] += av * w4.y;
                acc[r][2] += av * w4.z;
                acc[r][3] += av * w4.w;
            }
        }
        __syncthreads();
    }
    float4 bv = *(const float4*)&bp[cg * 4];
#pragma unroll
    for (int r = 0; r < RPT; r++) {
        size_t m = m0 + rg * RPT + r;
        float4 o;
        o.x = acc[r][0] + bv.x;
        o.y = acc[r][1] + bv.y;
        o.z = acc[r][2] + bv.z;
        o.w = acc[r][3] + bv.w;
        *(float4*)&Xg[m * N + cg * 4] = o;
    }
}

// ---------------------------------------------------------------------------
// LSTM scan, H=32: one warp per batch, lane = hidden unit. Whh in registers,
// h broadcast via shfl, split accumulators (2x16) to shorten FMA chains.
// hout != nullptr -> store all steps; lastout != nullptr -> store final h.
// ---------------------------------------------------------------------------
__global__ __launch_bounds__(32) void k_scan32(const float* __restrict__ xg,
                                               const float* __restrict__ whh,
                                               float* __restrict__ hout,
                                               float* __restrict__ lastout) {
    const int b = blockIdx.x;
    const int l = threadIdx.x;
    float wi[32], wf[32], wg[32], wo[32];
#pragma unroll
    for (int k = 0; k < 32; k++) {
        wi[k] = whh[(0 * 32 + l) * 32 + k];
        wf[k] = whh[(1 * 32 + l) * 32 + k];
        wg[k] = whh[(2 * 32 + l) * 32 + k];
        wo[k] = whh[(3 * 32 + l) * 32 + k];
    }
    float h = 0.f, c = 0.f;
    const float4* xgp = (const float4*)(xg + (size_t)b * TSEQ * 128) + l;
    for (int ts = 0; ts < TSEQ; ts++) {
        float4 a = xgp[(size_t)ts * 32];
        float gi0 = a.x, gf0 = a.y, gg0 = a.z, go0 = a.w;
        float gi1 = 0.f, gf1 = 0.f, gg1 = 0.f, go1 = 0.f;
#pragma unroll
        for (int k = 0; k < 16; k++) {
            float hk = __shfl_sync(0xffffffffu, h, k);
            gi0 += wi[k] * hk; gf0 += wf[k] * hk;
            gg0 += wg[k] * hk; go0 += wo[k] * hk;
            float hk2 = __shfl_sync(0xffffffffu, h, k + 16);
            gi1 += wi[k + 16] * hk2; gf1 += wf[k + 16] * hk2;
            gg1 += wg[k + 16] * hk2; go1 += wo[k + 16] * hk2;
        }
        c = sigf(gf0 + gf1) * c + sigf(gi0 + gi1) * tanha(gg0 + gg1);
        h = sigf(go0 + go1) * tanha(c);
        if (hout) hout[((size_t)b * TSEQ + ts) * 32 + l] = h;
    }
    if (lastout) lastout[b * 32 + l] = h;
}

// ---------------------------------------------------------------------------
// LSTM scan, H=16: two batches per warp (half-warps), shfl width 16.
// ---------------------------------------------------------------------------
__global__ __launch_bounds__(32) void k_scan16(const float* __restrict__ xg,
                                               const float* __restrict__ whh,
                                               float* __restrict__ hout) {
    const int lane = threadIdx.x;
    const int u = lane & 15;
    const int b = blockIdx.x * 2 + (lane >> 4);
    float wi[16], wf[16], wg[16], wo[16];
#pragma unroll
    for (int k = 0; k < 16; k++) {
        wi[k] = whh[(0 * 16 + u) * 16 + k];
        wf[k] = whh[(1 * 16 + u) * 16 + k];
        wg[k] = whh[(2 * 16 + u) * 16 + k];
        wo[k] = whh[(3 * 16 + u) * 16 + k];
    }
    float h = 0.f, c = 0.f;
    const float4* xgp = (const float4*)(xg + (size_t)b * TSEQ * 64) + u;
    for (int ts = 0; ts < TSEQ; ts++) {
        float4 a = xgp[(size_t)ts * 16];
        float gi = a.x, gf = a.y, gg = a.z, go = a.w;
#pragma unroll
        for (int k = 0; k < 16; k++) {
            float hk = __shfl_sync(0xffffffffu, h, k, 16);
            gi += wi[k] * hk; gf += wf[k] * hk;
            gg += wg[k] * hk; go += wo[k] * hk;
        }
        c = sigf(gf) * c + sigf(gi) * tanha(gg);
        h = sigf(go) * tanha(c);
        hout[((size_t)b * TSEQ + ts) * 16 + u] = h;
    }
}

// ---------------------------------------------------------------------------
extern "C" void kernel_launch(void* const* d_in, const int* in_sizes, int n_in,
                              void* d_out, int out_size) {
    const float* x      = (const float*)d_in[0];
    const float* conv_w = (const float*)d_in[1];
    const float* conv_b = (const float*)d_in[2];
    const float* Wih1   = (const float*)d_in[3];
    const float* Whh1   = (const float*)d_in[4];
    const float* bih1   = (const float*)d_in[5];
    const float* bhh1   = (const float*)d_in[6];
    const float* Wih2   = (const float*)d_in[7];
    const float* Whh2   = (const float*)d_in[8];
    const float* bih2   = (const float*)d_in[9];
    const float* bhh2   = (const float*)d_in[10];
    const float* Wih3   = (const float*)d_in[11];
    const float* Whh3   = (const float*)d_in[12];
    const float* bih3   = (const float*)d_in[13];
    const float* bhh3   = (const float*)d_in[14];
    float* out = (float*)d_out;

    float *p_conv, *p_xg1, *p_h1, *p_xg2, *p_h2, *p_xg3;
    float *p_w1p, *p_b1p, *p_w2p, *p_b2p, *p_w3p, *p_b3p;
    cudaGetSymbolAddress((void**)&p_conv, g_conv);
    cudaGetSymbolAddress((void**)&p_xg1,  g_xg1);
    cudaGetSymbolAddress((void**)&p_h1,   g_h1);
    cudaGetSymbolAddress((void**)&p_xg2,  g_xg2);
    cudaGetSymbolAddress((void**)&p_h2,   g_h2);
    cudaGetSymbolAddress((void**)&p_xg3,  g_xg3);
    cudaGetSymbolAddress((void**)&p_w1p,  g_w1p);
    cudaGetSymbolAddress((void**)&p_b1p,  g_b1p);
    cudaGetSymbolAddress((void**)&p_w2p,  g_w2p);
    cudaGetSymbolAddress((void**)&p_b2p,  g_b2p);
    cudaGetSymbolAddress((void**)&p_w3p,  g_w3p);
    cudaGetSymbolAddress((void**)&p_b3p,  g_b3p);

    // Weight/bias gate permutation (tiny)
    k_perm<<<64, 256>>>(Wih1, bih1, bhh1, p_w1p, p_b1p, 32, 128);
    k_perm<<<8,  256>>>(Wih2, bih2, bhh2, p_w2p, p_b2p, 16, 32);
    k_perm<<<8,  256>>>(Wih3, bih3, bhh3, p_w3p, p_b3p, 32, 16);

    // Conv: [512,128,1024] -> [512,128,1020]
    {
        dim3 grid(16, 2, BATCH);   // 16 l-tiles (64), 2 oc-tiles (64), per-batch
        k_conv<<<grid, 256>>>(x, conv_w, conv_b, p_conv);
    }

    const int GB = MROWS / 64;     // 8160 row-tiles

    // Layer 1: xg1 = conv(as [M][128]) @ W1p^T + b1p ; scan H=32
    k_gemm<128, 128><<<GB, 256>>>(p_conv, p_w1p, p_b1p, p_xg1);
    k_scan32<<<BATCH, 32>>>(p_xg1, Whh1, p_h1, nullptr);

    // Layer 2: xg2 = h1 @ W2p^T + b2p ; scan H=16
    k_gemm<64, 32><<<GB, 256>>>(p_h1, p_w2p, p_b2p, p_xg2);
    k_scan16<<<BATCH / 2, 32>>>(p_xg2, Whh2, p_h2);

    // Layer 3: xg3 = h2 @ W3p^T + b3p ; scan H=32, emit only final h -> d_out
    k_gemm<128, 16><<<GB, 256>>>(p_h2, p_w3p, p_b3p, p_xg3);
    k_scan32<<<BATCH, 32>>>(p_xg3, Whh3, nullptr, out);
}